// round 12
// baseline (speedup 1.0000x reference)
#include <cuda_runtime.h>
#include <cuda_bf16.h>
#include <cuda_fp16.h>
#include <math.h>

#define NN 100000
#define NP 100096          // padded ( >= 1563*64 = 100032 )
#define NBLK_UPD 1563
#define EI 800000
#define EE 400000
#define HD 128
#define GB 256
#define ND 35
#define NBLK_SCAN 98       // ceil(100000/1024)

typedef unsigned long long ull;

// ---------------- device scratch ----------------
__device__ float d_h [NN * HD];
__device__ float d_h2[NN * HD];
__device__ unsigned d_vp[NN * HD / 2];   // fp16x2 state
__device__ unsigned d_vl[NN * HD / 2];   // fp16x2 state
__device__ unsigned d_yi[NP * HD / 2];   // h @ W_intra, fp16x2 packed
__device__ unsigned d_ye[NP * HD / 2];   // h @ W_inter, fp16x2 packed
__device__ float d_wint[EE];
__device__ int   d_ecnt_i[NN];
__device__ int   d_ecnt_e[NN];
__device__ int   d_fill_i[NN];
__device__ int   d_fill_e[NN];
__device__ int   d_off_i[NN + 1];
__device__ int   d_off_e[NN + 1];
__device__ int   d_bsum_i[NBLK_SCAN];
__device__ int   d_bsum_e[NBLK_SCAN];
__device__ int   d_csrc_i[EI];
__device__ float d_cw_i[EI];
__device__ int   d_csrc_e[EE];
__device__ float d_cw_e[EE];
__device__ float d_cnti[NN];
__device__ float d_cnte[NN];
__device__ float d_invi[NN];
__device__ float d_loge[NN];
__device__ float d_pool[GB * HD];
__device__ float d_fcbuf[GB * HD];
// weight image: bf16 hi/lo split, transposed [n][k] pairs packed in 32-bit words.
__device__ unsigned d_wimg[4 * 2 * 2 * 128 * 64];

// ---------------- helpers ----------------
__device__ __forceinline__ float siluf(float v) { return v / (1.0f + expf(-v)); }

__device__ __forceinline__ void red_add_v4(float* p, float4 v) {
    asm volatile("red.global.add.v4.f32 [%0], {%1,%2,%3,%4};"
                 :: "l"(p), "f"(v.x), "f"(v.y), "f"(v.z), "f"(v.w) : "memory");
}

// d = {hi=bf16(a1), lo=bf16(a0)}
__device__ __forceinline__ unsigned bf16x2_of(float a0, float a1) {
    unsigned w;
    asm("cvt.rn.bf16x2.f32 %0, %1, %2;" : "=r"(w) : "f"(a1), "f"(a0));
    return w;
}

// d = {hi=f16(a1), lo=f16(a0)}
__device__ __forceinline__ unsigned f16x2_of(float a0, float a1) {
    unsigned w;
    asm("cvt.rn.f16x2.f32 %0, %1, %2;" : "=r"(w) : "f"(a1), "f"(a0));
    return w;
}

__device__ __forceinline__ float2 f16x2_to_f2(unsigned w) {
    __half2 h = *(__half2*)&w;
    return __half22float2(h);
}

__device__ __forceinline__ void mma16816(float* d, const unsigned* a, const unsigned* b) {
    asm volatile("mma.sync.aligned.m16n8k16.row.col.f32.bf16.bf16.f32 "
                 "{%0,%1,%2,%3}, {%4,%5,%6,%7}, {%8,%9}, {%0,%1,%2,%3};"
                 : "+f"(d[0]), "+f"(d[1]), "+f"(d[2]), "+f"(d[3])
                 : "r"(a[0]), "r"(a[1]), "r"(a[2]), "r"(a[3]), "r"(b[0]), "r"(b[1]));
}

// ---------------- init ----------------
__global__ void k_zero_pre() {
    int i = blockIdx.x * blockDim.x + threadIdx.x;
    if (i < NN) {
        d_ecnt_i[i] = 0; d_ecnt_e[i] = 0;
        d_fill_i[i] = 0; d_fill_e[i] = 0;
    }
    if (i < GB * HD) d_pool[i] = 0.0f;
}

// lin_node: h = silu(x @ W + b)   (vp/vl not touched: layer 0 skips reading them)
__global__ __launch_bounds__(128) void k_linnode(const float* __restrict__ x,
                                                 const float* __restrict__ W,
                                                 const float* __restrict__ b) {
    __shared__ float Ws[ND * HD];
    __shared__ float xs[8][ND];
    int t = threadIdx.x;
    for (int i = t; i < ND * HD; i += 128) Ws[i] = W[i];
    int n0 = blockIdx.x * 8;
    for (int i = t; i < 8 * ND; i += 128) {
        int nn = i / ND, k = i % ND;
        xs[nn][k] = x[(n0 + nn) * ND + k];
    }
    __syncthreads();
    float bb = b[t];
    for (int nn = 0; nn < 8; nn++) {
        int n = n0 + nn;
        float acc = bb;
#pragma unroll
        for (int k = 0; k < ND; k++) acc += xs[nn][k] * Ws[k * HD + t];
        d_h[n * HD + t] = siluf(acc);
    }
}

// ---------------- degrees + geometric weights (merged) ----------------
__global__ void k_deg(const int* __restrict__ ei, const int* __restrict__ ee,
                      const float* __restrict__ pos) {
    int e = blockIdx.x * blockDim.x + threadIdx.x;
    if (e < EI) atomicAdd(&d_ecnt_i[ei[EI + e]], 1);
    if (e < EE) {
        int s = ee[e], d = ee[EE + e];
        float dx = pos[s * 3 + 0] - pos[d * 3 + 0];
        float dy = pos[s * 3 + 1] - pos[d * 3 + 1];
        float dz = pos[s * 3 + 2] - pos[d * 3 + 2];
        d_wint[e] = expf(-(dx * dx + dy * dy + dz * dz));
        atomicAdd(&d_ecnt_e[d], 1);
    }
}

// ---------------- prefix scan (exclusive) -> CSR offsets ----------------
__global__ __launch_bounds__(1024) void k_scan_a(int which) {
    __shared__ int sh[1024];
    const int* cnt = which ? d_ecnt_e : d_ecnt_i;
    int* off = which ? d_off_e : d_off_i;
    int* bs  = which ? d_bsum_e : d_bsum_i;
    int tid = threadIdx.x;
    int i = blockIdx.x * 1024 + tid;
    int v = (i < NN) ? cnt[i] : 0;
    sh[tid] = v;
    __syncthreads();
#pragma unroll
    for (int o = 1; o < 1024; o <<= 1) {
        int u = (tid >= o) ? sh[tid - o] : 0;
        __syncthreads();
        sh[tid] += u;
        __syncthreads();
    }
    if (i <= NN) off[i] = sh[tid] - v;  // exclusive
    if (tid == 1023) bs[blockIdx.x] = sh[1023];
}

__global__ void k_scan_b() {
    if (threadIdx.x == 0) {
        int r = 0;
        for (int b = 0; b < NBLK_SCAN; b++) { int t = d_bsum_i[b]; d_bsum_i[b] = r; r += t; }
    }
    if (threadIdx.x == 1) {
        int r = 0;
        for (int b = 0; b < NBLK_SCAN; b++) { int t = d_bsum_e[b]; d_bsum_e[b] = r; r += t; }
    }
}

__global__ __launch_bounds__(1024) void k_scan_c(int which) {
    int* off = which ? d_off_e : d_off_i;
    const int* bs = which ? d_bsum_e : d_bsum_i;
    int i = blockIdx.x * 1024 + threadIdx.x;
    if (i <= NN) off[i] += bs[blockIdx.x];
}

// ---------------- CSR fill + degree factors (merged) ----------------
__global__ void k_fillf(const int* __restrict__ ei, const int* __restrict__ ee,
                        const float* __restrict__ ea) {
    int e = blockIdx.x * blockDim.x + threadIdx.x;
    if (e < NN) {
        float ci = (float)d_ecnt_i[e];
        float ce = (float)d_ecnt_e[e];
        d_cnti[e] = ci;
        d_cnte[e] = ce;
        d_invi[e] = 1.0f / (ci + 1.0f);
        d_loge[e] = logf(ce + 1.0f);
    }
    if (e < EI) {
        int s = ei[e], d = ei[EI + e];
        int p = d_off_i[d] + atomicAdd(&d_fill_i[d], 1);
        d_csrc_i[p] = s;
        d_cw_i[p] = ea[e];
    }
    if (e < EE) {
        int s = ee[e], d = ee[EE + e];
        int p = d_off_e[d] + atomicAdd(&d_fill_e[d], 1);
        d_csrc_e[p] = s;
        d_cw_e[p] = d_wint[e];
    }
}

// ---------------- weight prep: transpose + bf16 hi/lo split (once) ----------------
__global__ void k_prepw(const float* __restrict__ Wi, const float* __restrict__ We) {
    int gid = blockIdx.x * blockDim.x + threadIdx.x;
    if (gid >= 65536) return;
    int j = gid & 63;            // k-pair word
    int n = (gid >> 6) & 127;    // output col = B n-row
    int m = (gid >> 13) & 1;
    int l = gid >> 14;
    const float* Wsrc = (m ? We : Wi) + l * HD * HD;
    int k0 = 2 * j;
    float w0 = Wsrc[k0 * HD + n];
    float w1 = Wsrc[(k0 + 1) * HD + n];
    unsigned wh = bf16x2_of(w0, w1);
    float r0 = w0 - __uint_as_float(wh << 16);
    float r1 = w1 - __uint_as_float(wh & 0xffff0000u);
    unsigned wl = bf16x2_of(r0, r1);
    int pb = l * 4 + m * 2;
    d_wimg[(size_t)pb * 8192 + n * 64 + j] = wh;
    d_wimg[(size_t)(pb + 1) * 8192 + n * 64 + j] = wl;
}

// ---------------- k_trans: dense dual GEMM yi = h@Wi, ye = h@We (bf16 x3 split) ----------------
#define AWOFF(mp) (256 + (mp) * 2304)
#define WWOFF(mp) (9472 + (mp) * 4608)
#define UPD_SMEM 111616

__global__ __launch_bounds__(256, 2)
void k_trans(int layer, int parity) {
    extern __shared__ unsigned swm[];
    int t = threadIdx.x, lane = t & 31, wid = t >> 5;
    int n0 = blockIdx.x * 64;
    const float* __restrict__ hin = parity ? d_h2 : d_h;

    float acc_i[8][4], acc_e[8][4];
#pragma unroll
    for (int tt = 0; tt < 8; tt++)
#pragma unroll
        for (int q = 0; q < 4; q++) { acc_i[tt][q] = 0.f; acc_e[tt][q] = 0.f; }

    int strip = wid >> 1, half = wid & 1;
    int row = t >> 2, seg = t & 3;
    unsigned arowb = (unsigned)((strip * 16 + (lane >> 2)) * 36 + (lane & 3));
    unsigned browb = (unsigned)((half * 64 + (lane >> 2)) * 36 + (lane & 3));
    int nclamp = n0 + row < NN ? n0 + row : NN - 1;   // clamp tail rows (results discarded)

    for (int c = 0; c < 2; c++) {
        __syncthreads();
        // ---- stage A: fp32 h -> bf16 hi/lo ----
        {
            const float* src = hin + (size_t)nclamp * HD + c * 64 + seg * 16;
            unsigned hb = AWOFF(0) + row * 36 + seg * 8;
            unsigned lb = AWOFF(1) + row * 36 + seg * 8;
#pragma unroll
            for (int q = 0; q < 4; q++) {
                float4 v = ((const float4*)src)[q];
                unsigned wh0 = bf16x2_of(v.x, v.y);
                float r0 = v.x - __uint_as_float(wh0 << 16);
                float r1 = v.y - __uint_as_float(wh0 & 0xffff0000u);
                unsigned wl0 = bf16x2_of(r0, r1);
                unsigned wh1 = bf16x2_of(v.z, v.w);
                float r2 = v.z - __uint_as_float(wh1 << 16);
                float r3 = v.w - __uint_as_float(wh1 & 0xffff0000u);
                unsigned wl1 = bf16x2_of(r2, r3);
                swm[hb + q * 2]     = wh0;
                swm[hb + q * 2 + 1] = wh1;
                swm[lb + q * 2]     = wl0;
                swm[lb + q * 2 + 1] = wl1;
            }
        }
        // ---- stage W: copy prepped image chunk ----
#pragma unroll
        for (int mp = 0; mp < 4; mp++) {
            unsigned pbase = (unsigned)(layer * 4 + mp) * 8192 + c * 32;
#pragma unroll
            for (int uu = 0; uu < 4; uu++) {
                int u = t + uu * 256;
                int nrow = u >> 3, s = u & 7;
                int4 v = *(const int4*)(d_wimg + pbase + nrow * 64 + s * 4);
                *(int4*)(swm + WWOFF(mp) + nrow * 36 + s * 4) = v;
            }
        }
        __syncthreads();
        // ---- compute: 4 k-steps of 16 ----
#pragma unroll
        for (int s = 0; s < 4; s++) {
            unsigned ko = s * 8;
            unsigned a_h[4], a_l[4];
            a_h[0] = swm[AWOFF(0) + arowb + ko];
            a_h[1] = swm[AWOFF(0) + arowb + 288 + ko];
            a_h[2] = swm[AWOFF(0) + arowb + ko + 4];
            a_h[3] = swm[AWOFF(0) + arowb + 288 + ko + 4];
            a_l[0] = swm[AWOFF(1) + arowb + ko];
            a_l[1] = swm[AWOFF(1) + arowb + 288 + ko];
            a_l[2] = swm[AWOFF(1) + arowb + ko + 4];
            a_l[3] = swm[AWOFF(1) + arowb + 288 + ko + 4];
#pragma unroll
            for (int tt = 0; tt < 8; tt++) {
                unsigned bo = browb + tt * 288 + ko;
                unsigned bb[2];
                bb[0] = swm[WWOFF(0) + bo]; bb[1] = swm[WWOFF(0) + bo + 4];
                mma16816(acc_i[tt], a_h, bb);
                mma16816(acc_i[tt], a_l, bb);
                bb[0] = swm[WWOFF(1) + bo]; bb[1] = swm[WWOFF(1) + bo + 4];
                mma16816(acc_i[tt], a_h, bb);
                bb[0] = swm[WWOFF(2) + bo]; bb[1] = swm[WWOFF(2) + bo + 4];
                mma16816(acc_e[tt], a_h, bb);
                mma16816(acc_e[tt], a_l, bb);
                bb[0] = swm[WWOFF(3) + bo]; bb[1] = swm[WWOFF(3) + bo + 4];
                mma16816(acc_e[tt], a_h, bb);
            }
        }
    }

    // ---- store yi/ye as fp16x2 words (padded arrays: rows up to NP safe) ----
#pragma unroll
    for (int rr = 0; rr < 2; rr++) {
        int n = n0 + strip * 16 + (lane >> 2) + rr * 8;
#pragma unroll
        for (int tt = 0; tt < 8; tt++) {
            int cc = half * 64 + tt * 8 + (lane & 3) * 2;
            size_t woff = (size_t)n * 64 + (cc >> 1);
            d_yi[woff] = f16x2_of(acc_i[tt][rr * 2], acc_i[tt][rr * 2 + 1]);
            d_ye[woff] = f16x2_of(acc_e[tt][rr * 2], acc_e[tt][rr * 2 + 1]);
        }
    }
}

// ---------------- k_gath2: CSR gather of fp16 yi/ye + full epilogue ----------------
__global__ __launch_bounds__(256) void k_gath2(const float* __restrict__ bi,
                                               const float* __restrict__ be,
                                               const int* __restrict__ batch,
                                               int parity, int first, int last) {
    int g = blockIdx.x * 256 + threadIdx.x;
    int n = g >> 5;
    int lane = g & 31;
    if (n >= NN) return;
    const float* __restrict__ hin = parity ? d_h2 : d_h;
    float* hout = parity ? d_h : d_h2;

    // ---- hoisted epilogue loads: issue before the gather chains ----
    float ci = __ldg(d_cnti + n), inv = __ldg(d_invi + n);
    float ce = __ldg(d_cnte + n), lge = __ldg(d_loge + n);
    float4 bi4 = *(const float4*)(bi + lane * 4);
    float4 be4 = *(const float4*)(be + lane * 4);
    size_t off = (size_t)n * HD + lane * 4;
    size_t soff = (size_t)n * 64 + lane * 2;
    float4 hh = *(const float4*)(hin + off);
    float4 vp = make_float4(0.f, 0.f, 0.f, 0.f);
    float4 vl = make_float4(0.f, 0.f, 0.f, 0.f);
    if (!first) {
        uint2 vpw = *(const uint2*)(d_vp + soff);
        uint2 vlw = *(const uint2*)(d_vl + soff);
        float2 a = f16x2_to_f2(vpw.x), b2 = f16x2_to_f2(vpw.y);
        vp = make_float4(a.x, a.y, b2.x, b2.y);
        a = f16x2_to_f2(vlw.x); b2 = f16x2_to_f2(vlw.y);
        vl = make_float4(a.x, a.y, b2.x, b2.y);
    }
    int bb = last ? __ldg(batch + n) : 0;

    float4 si, se;
    // intra gather from yi (unroll 8: mean degree 8)
    {
        int p = d_off_i[n], pe = d_off_i[n + 1];
        float4 a0 = {0, 0, 0, 0}, a1 = {0, 0, 0, 0};
        for (; p + 8 <= pe; p += 8) {
            int s0 = __ldg(d_csrc_i + p);
            int s1 = __ldg(d_csrc_i + p + 1);
            int s2 = __ldg(d_csrc_i + p + 2);
            int s3 = __ldg(d_csrc_i + p + 3);
            int s4 = __ldg(d_csrc_i + p + 4);
            int s5 = __ldg(d_csrc_i + p + 5);
            int s6 = __ldg(d_csrc_i + p + 6);
            int s7 = __ldg(d_csrc_i + p + 7);
            float w0 = __ldg(d_cw_i + p);
            float w1 = __ldg(d_cw_i + p + 1);
            float w2 = __ldg(d_cw_i + p + 2);
            float w3 = __ldg(d_cw_i + p + 3);
            float w4 = __ldg(d_cw_i + p + 4);
            float w5 = __ldg(d_cw_i + p + 5);
            float w6 = __ldg(d_cw_i + p + 6);
            float w7 = __ldg(d_cw_i + p + 7);
            uint2 y0 = *(const uint2*)(d_yi + (size_t)s0 * 64 + lane * 2);
            uint2 y1 = *(const uint2*)(d_yi + (size_t)s1 * 64 + lane * 2);
            uint2 y2 = *(const uint2*)(d_yi + (size_t)s2 * 64 + lane * 2);
            uint2 y3 = *(const uint2*)(d_yi + (size_t)s3 * 64 + lane * 2);
            uint2 y4 = *(const uint2*)(d_yi + (size_t)s4 * 64 + lane * 2);
            uint2 y5 = *(const uint2*)(d_yi + (size_t)s5 * 64 + lane * 2);
            uint2 y6 = *(const uint2*)(d_yi + (size_t)s6 * 64 + lane * 2);
            uint2 y7 = *(const uint2*)(d_yi + (size_t)s7 * 64 + lane * 2);
            float2 fa, fb;
            fa = f16x2_to_f2(y0.x); fb = f16x2_to_f2(y0.y);
            a0.x += fa.x * w0; a0.y += fa.y * w0; a0.z += fb.x * w0; a0.w += fb.y * w0;
            fa = f16x2_to_f2(y1.x); fb = f16x2_to_f2(y1.y);
            a1.x += fa.x * w1; a1.y += fa.y * w1; a1.z += fb.x * w1; a1.w += fb.y * w1;
            fa = f16x2_to_f2(y2.x); fb = f16x2_to_f2(y2.y);
            a0.x += fa.x * w2; a0.y += fa.y * w2; a0.z += fb.x * w2; a0.w += fb.y * w2;
            fa = f16x2_to_f2(y3.x); fb = f16x2_to_f2(y3.y);
            a1.x += fa.x * w3; a1.y += fa.y * w3; a1.z += fb.x * w3; a1.w += fb.y * w3;
            fa = f16x2_to_f2(y4.x); fb = f16x2_to_f2(y4.y);
            a0.x += fa.x * w4; a0.y += fa.y * w4; a0.z += fb.x * w4; a0.w += fb.y * w4;
            fa = f16x2_to_f2(y5.x); fb = f16x2_to_f2(y5.y);
            a1.x += fa.x * w5; a1.y += fa.y * w5; a1.z += fb.x * w5; a1.w += fb.y * w5;
            fa = f16x2_to_f2(y6.x); fb = f16x2_to_f2(y6.y);
            a0.x += fa.x * w6; a0.y += fa.y * w6; a0.z += fb.x * w6; a0.w += fb.y * w6;
            fa = f16x2_to_f2(y7.x); fb = f16x2_to_f2(y7.y);
            a1.x += fa.x * w7; a1.y += fa.y * w7; a1.z += fb.x * w7; a1.w += fb.y * w7;
        }
        for (; p + 2 <= pe; p += 2) {
            int s0 = __ldg(d_csrc_i + p);
            int s1 = __ldg(d_csrc_i + p + 1);
            float w0 = __ldg(d_cw_i + p);
            float w1 = __ldg(d_cw_i + p + 1);
            uint2 y0 = *(const uint2*)(d_yi + (size_t)s0 * 64 + lane * 2);
            uint2 y1 = *(const uint2*)(d_yi + (size_t)s1 * 64 + lane * 2);
            float2 fa, fb;
            fa = f16x2_to_f2(y0.x); fb = f16x2_to_f2(y0.y);
            a0.x += fa.x * w0; a0.y += fa.y * w0; a0.z += fb.x * w0; a0.w += fb.y * w0;
            fa = f16x2_to_f2(y1.x); fb = f16x2_to_f2(y1.y);
            a1.x += fa.x * w1; a1.y += fa.y * w1; a1.z += fb.x * w1; a1.w += fb.y * w1;
        }
        if (p < pe) {
            int s0 = __ldg(d_csrc_i + p);
            float w0 = __ldg(d_cw_i + p);
            uint2 y0 = *(const uint2*)(d_yi + (size_t)s0 * 64 + lane * 2);
            float2 fa = f16x2_to_f2(y0.x), fb = f16x2_to_f2(y0.y);
            a0.x += fa.x * w0; a0.y += fa.y * w0; a0.z += fb.x * w0; a0.w += fb.y * w0;
        }
        si = make_float4(a0.x + a1.x, a0.y + a1.y, a0.z + a1.z, a0.w + a1.w);
    }
    // inter gather from ye (unroll 4: mean degree 4)
    {
        int p = d_off_e[n], pe = d_off_e[n + 1];
        float4 a0 = {0, 0, 0, 0}, a1 = {0, 0, 0, 0};
        for (; p + 4 <= pe; p += 4) {
            int s0 = __ldg(d_csrc_e + p);
            int s1 = __ldg(d_csrc_e + p + 1);
            int s2 = __ldg(d_csrc_e + p + 2);
            int s3 = __ldg(d_csrc_e + p + 3);
            float w0 = __ldg(d_cw_e + p);
            float w1 = __ldg(d_cw_e + p + 1);
            float w2 = __ldg(d_cw_e + p + 2);
            float w3 = __ldg(d_cw_e + p + 3);
            uint2 y0 = *(const uint2*)(d_ye + (size_t)s0 * 64 + lane * 2);
            uint2 y1 = *(const uint2*)(d_ye + (size_t)s1 * 64 + lane * 2);
            uint2 y2 = *(const uint2*)(d_ye + (size_t)s2 * 64 + lane * 2);
            uint2 y3 = *(const uint2*)(d_ye + (size_t)s3 * 64 + lane * 2);
            float2 fa, fb;
            fa = f16x2_to_f2(y0.x); fb = f16x2_to_f2(y0.y);
            a0.x += fa.x * w0; a0.y += fa.y * w0; a0.z += fb.x * w0; a0.w += fb.y * w0;
            fa = f16x2_to_f2(y1.x); fb = f16x2_to_f2(y1.y);
            a1.x += fa.x * w1; a1.y += fa.y * w1; a1.z += fb.x * w1; a1.w += fb.y * w1;
            fa = f16x2_to_f2(y2.x); fb = f16x2_to_f2(y2.y);
            a0.x += fa.x * w2; a0.y += fa.y * w2; a0.z += fb.x * w2; a0.w += fb.y * w2;
            fa = f16x2_to_f2(y3.x); fb = f16x2_to_f2(y3.y);
            a1.x += fa.x * w3; a1.y += fa.y * w3; a1.z += fb.x * w3; a1.w += fb.y * w3;
        }
        for (; p < pe; p++) {
            int s0 = __ldg(d_csrc_e + p);
            float w0 = __ldg(d_cw_e + p);
            uint2 y0 = *(const uint2*)(d_ye + (size_t)s0 * 64 + lane * 2);
            float2 fa = f16x2_to_f2(y0.x), fb = f16x2_to_f2(y0.y);
            a0.x += fa.x * w0; a0.y += fa.y * w0; a0.z += fb.x * w0; a0.w += fb.y * w0;
        }
        se = make_float4(a0.x + a1.x, a0.y + a1.y, a0.z + a1.z, a0.w + a1.w);
    }

    // ---- epilogue math ----
    float p0 = siluf((si.x + ci * bi4.x) * inv + vp.x);
    float p1 = siluf((si.y + ci * bi4.y) * inv + vp.y);
    float p2 = siluf((si.z + ci * bi4.z) * inv + vp.z);
    float p3 = siluf((si.w + ci * bi4.w) * inv + vp.w);
    float l0 = siluf((se.x + ce * be4.x) * lge + vl.x);
    float l1 = siluf((se.y + ce * be4.y) * lge + vl.y);
    float l2 = siluf((se.z + ce * be4.z) * lge + vl.z);
    float l3 = siluf((se.w + ce * be4.w) * lge + vl.w);
    float4 ho = make_float4(hh.x + p0 + l0, hh.y + p1 + l1, hh.z + p2 + l2, hh.w + p3 + l3);

    if (!last) {
        uint2 vpw = make_uint2(f16x2_of(p0, p1), f16x2_of(p2, p3));
        uint2 vlw = make_uint2(f16x2_of(l0, l1), f16x2_of(l2, l3));
        *(uint2*)(d_vp + soff) = vpw;
        *(uint2*)(d_vl + soff) = vlw;
        *(float4*)(hout + off) = ho;
    } else {
        red_add_v4(d_pool + bb * HD + lane * 4, ho);
    }
}

// ---------------- FC head ----------------
__global__ __launch_bounds__(128) void k_fc(const float* __restrict__ W,
                                            const float* __restrict__ b,
                                            const float* __restrict__ gam,
                                            const float* __restrict__ bet,
                                            int swap) {
    __shared__ float gr[HD];
    int bid = blockIdx.x;
    int t = threadIdx.x;
    const float* gin = swap ? d_fcbuf : d_pool;
    float* gout = swap ? d_pool : d_fcbuf;
    gr[t] = gin[bid * HD + t];
    __syncthreads();
    float acc = b[t];
#pragma unroll 8
    for (int k = 0; k < HD; k++) acc += gr[k] * W[k * HD + t];
    acc = acc > 0.f ? acc : 0.01f * acc;
    float bnscale = rsqrtf(1.0f + 1e-5f);
    acc = acc * bnscale * gam[t] + bet[t];
    gout[bid * HD + t] = acc;
}

__global__ __launch_bounds__(128) void k_out(const float* __restrict__ oW,
                                             const float* __restrict__ ob,
                                             float* __restrict__ out) {
    __shared__ float part[4];
    int b = blockIdx.x;
    int t = threadIdx.x;
    float p = d_fcbuf[b * HD + t] * oW[t];
#pragma unroll
    for (int o = 16; o > 0; o >>= 1) p += __shfl_down_sync(0xffffffffu, p, o);
    if ((t & 31) == 0) part[t >> 5] = p;
    __syncthreads();
    if (t == 0) out[b] = part[0] + part[1] + part[2] + part[3] + ob[0];
}

// ---------------- host launcher ----------------
extern "C" void kernel_launch(void* const* d_in, const int* in_sizes, int n_in,
                              void* d_out, int out_size) {
    const float* x     = (const float*)d_in[0];
    const int*   ei    = (const int*)d_in[1];
    const int*   ee    = (const int*)d_in[2];
    const float* pos   = (const float*)d_in[3];
    const float* eattr = (const float*)d_in[4];
    const int*   batch = (const int*)d_in[5];
    const float* lnW   = (const float*)d_in[6];
    const float* lnb   = (const float*)d_in[7];
    const float* Wi    = (const float*)d_in[8];
    const float* bi    = (const float*)d_in[9];
    const float* We    = (const float*)d_in[10];
    const float* be    = (const float*)d_in[11];
    const float* fcW   = (const float*)d_in[12];
    const float* fcb   = (const float*)d_in[13];
    const float* gam   = (const float*)d_in[14];
    const float* bet   = (const float*)d_in[15];
    const float* oW    = (const float*)d_in[16];
    const float* ob    = (const float*)d_in[17];
    float* out = (float*)d_out;

    static int smem_set = 0;
    if (!smem_set) {
        cudaFuncSetAttribute(k_trans, cudaFuncAttributeMaxDynamicSharedMemorySize, UPD_SMEM);
        smem_set = 1;
    }

    k_zero_pre<<<(NN + 255) / 256, 256>>>();
    k_linnode<<<NN / 8, 128>>>(x, lnW, lnb);
    k_deg<<<(EI + 255) / 256, 256>>>(ei, ee, pos);
    k_prepw<<<256, 256>>>(Wi, We);

    k_scan_a<<<NBLK_SCAN, 1024>>>(0);
    k_scan_a<<<NBLK_SCAN, 1024>>>(1);
    k_scan_b<<<1, 32>>>();
    k_scan_c<<<NBLK_SCAN, 1024>>>(0);
    k_scan_c<<<NBLK_SCAN, 1024>>>(1);
    k_fillf<<<(EI + 255) / 256, 256>>>(ei, ee, eattr);

    for (int l = 0; l < 4; l++) {
        k_trans<<<NBLK_UPD, 256, UPD_SMEM>>>(l, l & 1);
        k_gath2<<<(NN * 32 + 255) / 256, 256>>>(bi + l * HD, be + l * HD, batch,
                                                l & 1, l == 0, l == 3);
    }

    k_fc<<<GB, 128>>>(fcW + 0 * HD * HD, fcb + 0 * HD, gam + 0 * HD, bet + 0 * HD, 0);
    k_fc<<<GB, 128>>>(fcW + 1 * HD * HD, fcb + 1 * HD, gam + 1 * HD, bet + 1 * HD, 1);
    k_fc<<<GB, 128>>>(fcW + 2 * HD * HD, fcb + 2 * HD, gam + 2 * HD, bet + 2 * HD, 0);
    k_out<<<GB, 128>>>(oW, ob, out);
}

// round 15
// speedup vs baseline: 1.1728x; 1.1728x over previous
#include <cuda_runtime.h>
#include <cuda_bf16.h>
#include <cuda_fp16.h>
#include <math.h>

#define NN 100000
#define NP 100096          // padded ( >= 1563*64 = 100032 )
#define NBLK_UPD 1563
#define EI 800000
#define EE 400000
#define HD 128
#define GB 256
#define ND 35
#define NBLK_SCAN 98       // ceil(100000/1024)

typedef unsigned long long ull;

// ---------------- device scratch ----------------
__device__ float d_h [NN * HD];
__device__ float d_h2[NN * HD];
__device__ unsigned d_vp[NN * HD / 2];   // fp16x2 state
__device__ unsigned d_vl[NN * HD / 2];   // fp16x2 state
__device__ unsigned d_yi[NP * HD / 2];   // h @ W_intra, fp16x2 packed
__device__ unsigned d_ye[NP * HD / 2];   // h @ W_inter, fp16x2 packed
__device__ float d_wint[EE];
__device__ int   d_ecnt_i[NN];
__device__ int   d_ecnt_e[NN];
__device__ int   d_fill_i[NN];
__device__ int   d_fill_e[NN];
__device__ int   d_off_i[NN + 1];
__device__ int   d_off_e[NN + 1];
__device__ int   d_bsum_i[NBLK_SCAN];
__device__ int   d_bsum_e[NBLK_SCAN];
__device__ int   d_csrc_i[EI];
__device__ float d_cw_i[EI];
__device__ int   d_csrc_e[EE];
__device__ float d_cw_e[EE];
__device__ float d_cnti[NN];
__device__ float d_cnte[NN];
__device__ float d_invi[NN];
__device__ float d_loge[NN];
__device__ float d_pool[GB * HD];
__device__ float d_fcbuf[GB * HD];
// weight image: fp16, transposed [n][k] pairs packed in 32-bit words.
// piece index pb = layer*2 + mat; each piece = 128 n-rows x 64 k-words.
__device__ unsigned d_wimg[4 * 2 * 128 * 64];

// ---------------- helpers ----------------
__device__ __forceinline__ float siluf(float v) { return v / (1.0f + expf(-v)); }

__device__ __forceinline__ void red_add_v4(float* p, float4 v) {
    asm volatile("red.global.add.v4.f32 [%0], {%1,%2,%3,%4};"
                 :: "l"(p), "f"(v.x), "f"(v.y), "f"(v.z), "f"(v.w) : "memory");
}

// d = {hi=f16(a1), lo=f16(a0)}
__device__ __forceinline__ unsigned f16x2_of(float a0, float a1) {
    unsigned w;
    asm("cvt.rn.f16x2.f32 %0, %1, %2;" : "=r"(w) : "f"(a1), "f"(a0));
    return w;
}

__device__ __forceinline__ float2 f16x2_to_f2(unsigned w) {
    __half2 h = *(__half2*)&w;
    return __half22float2(h);
}

__device__ __forceinline__ void mma16816h(float* d, const unsigned* a, const unsigned* b) {
    asm volatile("mma.sync.aligned.m16n8k16.row.col.f32.f16.f16.f32 "
                 "{%0,%1,%2,%3}, {%4,%5,%6,%7}, {%8,%9}, {%0,%1,%2,%3};"
                 : "+f"(d[0]), "+f"(d[1]), "+f"(d[2]), "+f"(d[3])
                 : "r"(a[0]), "r"(a[1]), "r"(a[2]), "r"(a[3]), "r"(b[0]), "r"(b[1]));
}

// ---------------- init ----------------
__global__ void k_zero_pre() {
    int i = blockIdx.x * blockDim.x + threadIdx.x;
    if (i < NN) {
        d_ecnt_i[i] = 0; d_ecnt_e[i] = 0;
        d_fill_i[i] = 0; d_fill_e[i] = 0;
    }
    if (i < GB * HD) d_pool[i] = 0.0f;
}

// lin_node: h = silu(x @ W + b)   (vp/vl not touched: layer 0 skips reading them)
__global__ __launch_bounds__(128) void k_linnode(const float* __restrict__ x,
                                                 const float* __restrict__ W,
                                                 const float* __restrict__ b) {
    __shared__ float Ws[ND * HD];
    __shared__ float xs[8][ND];
    int t = threadIdx.x;
    for (int i = t; i < ND * HD; i += 128) Ws[i] = W[i];
    int n0 = blockIdx.x * 8;
    for (int i = t; i < 8 * ND; i += 128) {
        int nn = i / ND, k = i % ND;
        xs[nn][k] = x[(n0 + nn) * ND + k];
    }
    __syncthreads();
    float bb = b[t];
    for (int nn = 0; nn < 8; nn++) {
        int n = n0 + nn;
        float acc = bb;
#pragma unroll
        for (int k = 0; k < ND; k++) acc += xs[nn][k] * Ws[k * HD + t];
        d_h[n * HD + t] = siluf(acc);
    }
}

// ---------------- degrees + geometric weights (merged) ----------------
__global__ void k_deg(const int* __restrict__ ei, const int* __restrict__ ee,
                      const float* __restrict__ pos) {
    int e = blockIdx.x * blockDim.x + threadIdx.x;
    if (e < EI) atomicAdd(&d_ecnt_i[ei[EI + e]], 1);
    if (e < EE) {
        int s = ee[e], d = ee[EE + e];
        float dx = pos[s * 3 + 0] - pos[d * 3 + 0];
        float dy = pos[s * 3 + 1] - pos[d * 3 + 1];
        float dz = pos[s * 3 + 2] - pos[d * 3 + 2];
        d_wint[e] = expf(-(dx * dx + dy * dy + dz * dz));
        atomicAdd(&d_ecnt_e[d], 1);
    }
}

// ---------------- prefix scan (exclusive) -> CSR offsets ----------------
__global__ __launch_bounds__(1024) void k_scan_a(int which) {
    __shared__ int sh[1024];
    const int* cnt = which ? d_ecnt_e : d_ecnt_i;
    int* off = which ? d_off_e : d_off_i;
    int* bs  = which ? d_bsum_e : d_bsum_i;
    int tid = threadIdx.x;
    int i = blockIdx.x * 1024 + tid;
    int v = (i < NN) ? cnt[i] : 0;
    sh[tid] = v;
    __syncthreads();
#pragma unroll
    for (int o = 1; o < 1024; o <<= 1) {
        int u = (tid >= o) ? sh[tid - o] : 0;
        __syncthreads();
        sh[tid] += u;
        __syncthreads();
    }
    if (i <= NN) off[i] = sh[tid] - v;  // exclusive
    if (tid == 1023) bs[blockIdx.x] = sh[1023];
}

__global__ void k_scan_b() {
    if (threadIdx.x == 0) {
        int r = 0;
        for (int b = 0; b < NBLK_SCAN; b++) { int t = d_bsum_i[b]; d_bsum_i[b] = r; r += t; }
    }
    if (threadIdx.x == 1) {
        int r = 0;
        for (int b = 0; b < NBLK_SCAN; b++) { int t = d_bsum_e[b]; d_bsum_e[b] = r; r += t; }
    }
}

__global__ __launch_bounds__(1024) void k_scan_c(int which) {
    int* off = which ? d_off_e : d_off_i;
    const int* bs = which ? d_bsum_e : d_bsum_i;
    int i = blockIdx.x * 1024 + threadIdx.x;
    if (i <= NN) off[i] += bs[blockIdx.x];
}

// ---------------- CSR fill + degree factors (merged) ----------------
__global__ void k_fillf(const int* __restrict__ ei, const int* __restrict__ ee,
                        const float* __restrict__ ea) {
    int e = blockIdx.x * blockDim.x + threadIdx.x;
    if (e < NN) {
        float ci = (float)d_ecnt_i[e];
        float ce = (float)d_ecnt_e[e];
        d_cnti[e] = ci;
        d_cnte[e] = ce;
        d_invi[e] = 1.0f / (ci + 1.0f);
        d_loge[e] = logf(ce + 1.0f);
    }
    if (e < EI) {
        int s = ei[e], d = ei[EI + e];
        int p = d_off_i[d] + atomicAdd(&d_fill_i[d], 1);
        d_csrc_i[p] = s;
        d_cw_i[p] = ea[e];
    }
    if (e < EE) {
        int s = ee[e], d = ee[EE + e];
        int p = d_off_e[d] + atomicAdd(&d_fill_e[d], 1);
        d_csrc_e[p] = s;
        d_cw_e[p] = d_wint[e];
    }
}

// ---------------- weight prep: transpose + fp16 pack (once) ----------------
__global__ void k_prepw(const float* __restrict__ Wi, const float* __restrict__ We) {
    int gid = blockIdx.x * blockDim.x + threadIdx.x;
    if (gid >= 65536) return;
    int j = gid & 63;            // k-pair word
    int n = (gid >> 6) & 127;    // output col = B n-row
    int m = (gid >> 13) & 1;
    int l = gid >> 14;
    const float* Wsrc = (m ? We : Wi) + l * HD * HD;
    int k0 = 2 * j;
    float w0 = Wsrc[k0 * HD + n];
    float w1 = Wsrc[(k0 + 1) * HD + n];
    int pb = l * 2 + m;
    d_wimg[(size_t)pb * 8192 + n * 64 + j] = f16x2_of(w0, w1);
}

// ---------------- k_trans: dense dual GEMM yi = h@Wi, ye = h@We (fp16 single) ----------------
// 64 node-rows per block, 256 threads = 8 warps = 4 row-strips(m16) x 2 col-halves(n64).
// Padded smem rows: 36 words (32 data + 4 skew).
// smem words: bias-pad[256] | A fp16 64x36 | W fp16 2 x 128x36
#define AWOFF    256
#define WWOFF(m) (2560 + (m) * 4608)
#define UPD_SMEM 47104

__global__ __launch_bounds__(256)
void k_trans(int layer, int parity) {
    extern __shared__ unsigned swm[];
    int t = threadIdx.x, lane = t & 31, wid = t >> 5;
    int n0 = blockIdx.x * 64;
    const float* __restrict__ hin = parity ? d_h2 : d_h;

    float acc_i[8][4], acc_e[8][4];
#pragma unroll
    for (int tt = 0; tt < 8; tt++)
#pragma unroll
        for (int q = 0; q < 4; q++) { acc_i[tt][q] = 0.f; acc_e[tt][q] = 0.f; }

    int strip = wid >> 1, half = wid & 1;
    int row = t >> 2, seg = t & 3;
    unsigned arowb = (unsigned)((strip * 16 + (lane >> 2)) * 36 + (lane & 3));
    unsigned browb = (unsigned)((half * 64 + (lane >> 2)) * 36 + (lane & 3));
    int nclamp = n0 + row < NN ? n0 + row : NN - 1;   // clamp tail rows (results discarded)

    for (int c = 0; c < 2; c++) {
        __syncthreads();
        // ---- stage A: fp32 h -> fp16 ----
        {
            const float* src = hin + (size_t)nclamp * HD + c * 64 + seg * 16;
            unsigned ab = AWOFF + row * 36 + seg * 8;
#pragma unroll
            for (int q = 0; q < 4; q++) {
                float4 v = ((const float4*)src)[q];
                swm[ab + q * 2]     = f16x2_of(v.x, v.y);
                swm[ab + q * 2 + 1] = f16x2_of(v.z, v.w);
            }
        }
        // ---- stage W: copy prepped fp16 image chunk (2 pieces) ----
#pragma unroll
        for (int mp = 0; mp < 2; mp++) {
            unsigned pbase = (unsigned)(layer * 2 + mp) * 8192 + c * 32;
#pragma unroll
            for (int uu = 0; uu < 4; uu++) {
                int u = t + uu * 256;
                int nrow = u >> 3, s = u & 7;
                int4 v = *(const int4*)(d_wimg + pbase + nrow * 64 + s * 4);
                *(int4*)(swm + WWOFF(mp) + nrow * 36 + s * 4) = v;
            }
        }
        __syncthreads();
        // ---- compute: 4 k-steps of 16 ----
#pragma unroll
        for (int s = 0; s < 4; s++) {
            unsigned ko = s * 8;
            unsigned aa[4];
            aa[0] = swm[AWOFF + arowb + ko];
            aa[1] = swm[AWOFF + arowb + 288 + ko];
            aa[2] = swm[AWOFF + arowb + ko + 4];
            aa[3] = swm[AWOFF + arowb + 288 + ko + 4];
#pragma unroll
            for (int tt = 0; tt < 8; tt++) {
                unsigned bo = browb + tt * 288 + ko;
                unsigned bb[2];
                bb[0] = swm[WWOFF(0) + bo]; bb[1] = swm[WWOFF(0) + bo + 4];
                mma16816h(acc_i[tt], aa, bb);
                bb[0] = swm[WWOFF(1) + bo]; bb[1] = swm[WWOFF(1) + bo + 4];
                mma16816h(acc_e[tt], aa, bb);
            }
        }
    }

    // ---- store yi/ye as fp16x2 words (padded arrays: rows up to NP safe) ----
#pragma unroll
    for (int rr = 0; rr < 2; rr++) {
        int n = n0 + strip * 16 + (lane >> 2) + rr * 8;
#pragma unroll
        for (int tt = 0; tt < 8; tt++) {
            int cc = half * 64 + tt * 8 + (lane & 3) * 2;
            size_t woff = (size_t)n * 64 + (cc >> 1);
            d_yi[woff] = f16x2_of(acc_i[tt][rr * 2], acc_i[tt][rr * 2 + 1]);
            d_ye[woff] = f16x2_of(acc_e[tt][rr * 2], acc_e[tt][rr * 2 + 1]);
        }
    }
}

// ---------------- k_gath2: CSR gather of fp16 yi/ye + full epilogue ----------------
__global__ __launch_bounds__(256) void k_gath2(const float* __restrict__ bi,
                                               const float* __restrict__ be,
                                               const int* __restrict__ batch,
                                               int parity, int first, int last) {
    int g = blockIdx.x * 256 + threadIdx.x;
    int n = g >> 5;
    int lane = g & 31;
    if (n >= NN) return;
    const float* __restrict__ hin = parity ? d_h2 : d_h;
    float* hout = parity ? d_h : d_h2;

    // ---- hoisted epilogue loads: issue before the gather chains ----
    float ci = __ldg(d_cnti + n), inv = __ldg(d_invi + n);
    float ce = __ldg(d_cnte + n), lge = __ldg(d_loge + n);
    float4 bi4 = *(const float4*)(bi + lane * 4);
    float4 be4 = *(const float4*)(be + lane * 4);
    size_t off = (size_t)n * HD + lane * 4;
    size_t soff = (size_t)n * 64 + lane * 2;
    float4 hh = *(const float4*)(hin + off);
    float4 vp = make_float4(0.f, 0.f, 0.f, 0.f);
    float4 vl = make_float4(0.f, 0.f, 0.f, 0.f);
    if (!first) {
        uint2 vpw = *(const uint2*)(d_vp + soff);
        uint2 vlw = *(const uint2*)(d_vl + soff);
        float2 a = f16x2_to_f2(vpw.x), b2 = f16x2_to_f2(vpw.y);
        vp = make_float4(a.x, a.y, b2.x, b2.y);
        a = f16x2_to_f2(vlw.x); b2 = f16x2_to_f2(vlw.y);
        vl = make_float4(a.x, a.y, b2.x, b2.y);
    }
    int bb = last ? __ldg(batch + n) : 0;

    float4 si, se;
    // intra gather from yi (unroll 8: mean degree 8)
    {
        int p = d_off_i[n], pe = d_off_i[n + 1];
        float4 a0 = {0, 0, 0, 0}, a1 = {0, 0, 0, 0};
        for (; p + 8 <= pe; p += 8) {
            int s0 = __ldg(d_csrc_i + p);
            int s1 = __ldg(d_csrc_i + p + 1);
            int s2 = __ldg(d_csrc_i + p + 2);
            int s3 = __ldg(d_csrc_i + p + 3);
            int s4 = __ldg(d_csrc_i + p + 4);
            int s5 = __ldg(d_csrc_i + p + 5);
            int s6 = __ldg(d_csrc_i + p + 6);
            int s7 = __ldg(d_csrc_i + p + 7);
            float w0 = __ldg(d_cw_i + p);
            float w1 = __ldg(d_cw_i + p + 1);
            float w2 = __ldg(d_cw_i + p + 2);
            float w3 = __ldg(d_cw_i + p + 3);
            float w4 = __ldg(d_cw_i + p + 4);
            float w5 = __ldg(d_cw_i + p + 5);
            float w6 = __ldg(d_cw_i + p + 6);
            float w7 = __ldg(d_cw_i + p + 7);
            uint2 y0 = *(const uint2*)(d_yi + (size_t)s0 * 64 + lane * 2);
            uint2 y1 = *(const uint2*)(d_yi + (size_t)s1 * 64 + lane * 2);
            uint2 y2 = *(const uint2*)(d_yi + (size_t)s2 * 64 + lane * 2);
            uint2 y3 = *(const uint2*)(d_yi + (size_t)s3 * 64 + lane * 2);
            uint2 y4 = *(const uint2*)(d_yi + (size_t)s4 * 64 + lane * 2);
            uint2 y5 = *(const uint2*)(d_yi + (size_t)s5 * 64 + lane * 2);
            uint2 y6 = *(const uint2*)(d_yi + (size_t)s6 * 64 + lane * 2);
            uint2 y7 = *(const uint2*)(d_yi + (size_t)s7 * 64 + lane * 2);
            float2 fa, fb;
            fa = f16x2_to_f2(y0.x); fb = f16x2_to_f2(y0.y);
            a0.x += fa.x * w0; a0.y += fa.y * w0; a0.z += fb.x * w0; a0.w += fb.y * w0;
            fa = f16x2_to_f2(y1.x); fb = f16x2_to_f2(y1.y);
            a1.x += fa.x * w1; a1.y += fa.y * w1; a1.z += fb.x * w1; a1.w += fb.y * w1;
            fa = f16x2_to_f2(y2.x); fb = f16x2_to_f2(y2.y);
            a0.x += fa.x * w2; a0.y += fa.y * w2; a0.z += fb.x * w2; a0.w += fb.y * w2;
            fa = f16x2_to_f2(y3.x); fb = f16x2_to_f2(y3.y);
            a1.x += fa.x * w3; a1.y += fa.y * w3; a1.z += fb.x * w3; a1.w += fb.y * w3;
            fa = f16x2_to_f2(y4.x); fb = f16x2_to_f2(y4.y);
            a0.x += fa.x * w4; a0.y += fa.y * w4; a0.z += fb.x * w4; a0.w += fb.y * w4;
            fa = f16x2_to_f2(y5.x); fb = f16x2_to_f2(y5.y);
            a1.x += fa.x * w5; a1.y += fa.y * w5; a1.z += fb.x * w5; a1.w += fb.y * w5;
            fa = f16x2_to_f2(y6.x); fb = f16x2_to_f2(y6.y);
            a0.x += fa.x * w6; a0.y += fa.y * w6; a0.z += fb.x * w6; a0.w += fb.y * w6;
            fa = f16x2_to_f2(y7.x); fb = f16x2_to_f2(y7.y);
            a1.x += fa.x * w7; a1.y += fa.y * w7; a1.z += fb.x * w7; a1.w += fb.y * w7;
        }
        for (; p + 2 <= pe; p += 2) {
            int s0 = __ldg(d_csrc_i + p);
            int s1 = __ldg(d_csrc_i + p + 1);
            float w0 = __ldg(d_cw_i + p);
            float w1 = __ldg(d_cw_i + p + 1);
            uint2 y0 = *(const uint2*)(d_yi + (size_t)s0 * 64 + lane * 2);
            uint2 y1 = *(const uint2*)(d_yi + (size_t)s1 * 64 + lane * 2);
            float2 fa, fb;
            fa = f16x2_to_f2(y0.x); fb = f16x2_to_f2(y0.y);
            a0.x += fa.x * w0; a0.y += fa.y * w0; a0.z += fb.x * w0; a0.w += fb.y * w0;
            fa = f16x2_to_f2(y1.x); fb = f16x2_to_f2(y1.y);
            a1.x += fa.x * w1; a1.y += fa.y * w1; a1.z += fb.x * w1; a1.w += fb.y * w1;
        }
        if (p < pe) {
            int s0 = __ldg(d_csrc_i + p);
            float w0 = __ldg(d_cw_i + p);
            uint2 y0 = *(const uint2*)(d_yi + (size_t)s0 * 64 + lane * 2);
            float2 fa = f16x2_to_f2(y0.x), fb = f16x2_to_f2(y0.y);
            a0.x += fa.x * w0; a0.y += fa.y * w0; a0.z += fb.x * w0; a0.w += fb.y * w0;
        }
        si = make_float4(a0.x + a1.x, a0.y + a1.y, a0.z + a1.z, a0.w + a1.w);
    }
    // inter gather from ye (unroll 4: mean degree 4)
    {
        int p = d_off_e[n], pe = d_off_e[n + 1];
        float4 a0 = {0, 0, 0, 0}, a1 = {0, 0, 0, 0};
        for (; p + 4 <= pe; p += 4) {
            int s0 = __ldg(d_csrc_e + p);
            int s1 = __ldg(d_csrc_e + p + 1);
            int s2 = __ldg(d_csrc_e + p + 2);
            int s3 = __ldg(d_csrc_e + p + 3);
            float w0 = __ldg(d_cw_e + p);
            float w1 = __ldg(d_cw_e + p + 1);
            float w2 = __ldg(d_cw_e + p + 2);
            float w3 = __ldg(d_cw_e + p + 3);
            uint2 y0 = *(const uint2*)(d_ye + (size_t)s0 * 64 + lane * 2);
            uint2 y1 = *(const uint2*)(d_ye + (size_t)s1 * 64 + lane * 2);
            uint2 y2 = *(const uint2*)(d_ye + (size_t)s2 * 64 + lane * 2);
            uint2 y3 = *(const uint2*)(d_ye + (size_t)s3 * 64 + lane * 2);
            float2 fa, fb;
            fa = f16x2_to_f2(y0.x); fb = f16x2_to_f2(y0.y);
            a0.x += fa.x * w0; a0.y += fa.y * w0; a0.z += fb.x * w0; a0.w += fb.y * w0;
            fa = f16x2_to_f2(y1.x); fb = f16x2_to_f2(y1.y);
            a1.x += fa.x * w1; a1.y += fa.y * w1; a1.z += fb.x * w1; a1.w += fb.y * w1;
            fa = f16x2_to_f2(y2.x); fb = f16x2_to_f2(y2.y);
            a0.x += fa.x * w2; a0.y += fa.y * w2; a0.z += fb.x * w2; a0.w += fb.y * w2;
            fa = f16x2_to_f2(y3.x); fb = f16x2_to_f2(y3.y);
            a1.x += fa.x * w3; a1.y += fa.y * w3; a1.z += fb.x * w3; a1.w += fb.y * w3;
        }
        for (; p < pe; p++) {
            int s0 = __ldg(d_csrc_e + p);
            float w0 = __ldg(d_cw_e + p);
            uint2 y0 = *(const uint2*)(d_ye + (size_t)s0 * 64 + lane * 2);
            float2 fa = f16x2_to_f2(y0.x), fb = f16x2_to_f2(y0.y);
            a0.x += fa.x * w0; a0.y += fa.y * w0; a0.z += fb.x * w0; a0.w += fb.y * w0;
        }
        se = make_float4(a0.x + a1.x, a0.y + a1.y, a0.z + a1.z, a0.w + a1.w);
    }

    // ---- epilogue math ----
    float p0 = siluf((si.x + ci * bi4.x) * inv + vp.x);
    float p1 = siluf((si.y + ci * bi4.y) * inv + vp.y);
    float p2 = siluf((si.z + ci * bi4.z) * inv + vp.z);
    float p3 = siluf((si.w + ci * bi4.w) * inv + vp.w);
    float l0 = siluf((se.x + ce * be4.x) * lge + vl.x);
    float l1 = siluf((se.y + ce * be4.y) * lge + vl.y);
    float l2 = siluf((se.z + ce * be4.z) * lge + vl.z);
    float l3 = siluf((se.w + ce * be4.w) * lge + vl.w);
    float4 ho = make_float4(hh.x + p0 + l0, hh.y + p1 + l1, hh.z + p2 + l2, hh.w + p3 + l3);

    if (!last) {
        uint2 vpw = make_uint2(f16x2_of(p0, p1), f16x2_of(p2, p3));
        uint2 vlw = make_uint2(f16x2_of(l0, l1), f16x2_of(l2, l3));
        *(uint2*)(d_vp + soff) = vpw;
        *(uint2*)(d_vl + soff) = vlw;
        *(float4*)(hout + off) = ho;
    } else {
        red_add_v4(d_pool + bb * HD + lane * 4, ho);
    }
}

// ---------------- FC head ----------------
__global__ __launch_bounds__(128) void k_fc(const float* __restrict__ W,
                                            const float* __restrict__ b,
                                            const float* __restrict__ gam,
                                            const float* __restrict__ bet,
                                            int swap) {
    __shared__ float gr[HD];
    int bid = blockIdx.x;
    int t = threadIdx.x;
    const float* gin = swap ? d_fcbuf : d_pool;
    float* gout = swap ? d_pool : d_fcbuf;
    gr[t] = gin[bid * HD + t];
    __syncthreads();
    float acc = b[t];
#pragma unroll 8
    for (int k = 0; k < HD; k++) acc += gr[k] * W[k * HD + t];
    acc = acc > 0.f ? acc : 0.01f * acc;
    float bnscale = rsqrtf(1.0f + 1e-5f);
    acc = acc * bnscale * gam[t] + bet[t];
    gout[bid * HD + t] = acc;
}

__global__ __launch_bounds__(128) void k_out(const float* __restrict__ oW,
                                             const float* __restrict__ ob,
                                             float* __restrict__ out) {
    __shared__ float part[4];
    int b = blockIdx.x;
    int t = threadIdx.x;
    float p = d_fcbuf[b * HD + t] * oW[t];
#pragma unroll
    for (int o = 16; o > 0; o >>= 1) p += __shfl_down_sync(0xffffffffu, p, o);
    if ((t & 31) == 0) part[t >> 5] = p;
    __syncthreads();
    if (t == 0) out[b] = part[0] + part[1] + part[2] + part[3] + ob[0];
}

// ---------------- host launcher ----------------
extern "C" void kernel_launch(void* const* d_in, const int* in_sizes, int n_in,
                              void* d_out, int out_size) {
    const float* x     = (const float*)d_in[0];
    const int*   ei    = (const int*)d_in[1];
    const int*   ee    = (const int*)d_in[2];
    const float* pos   = (const float*)d_in[3];
    const float* eattr = (const float*)d_in[4];
    const int*   batch = (const int*)d_in[5];
    const float* lnW   = (const float*)d_in[6];
    const float* lnb   = (const float*)d_in[7];
    const float* Wi    = (const float*)d_in[8];
    const float* bi    = (const float*)d_in[9];
    const float* We    = (const float*)d_in[10];
    const float* be    = (const float*)d_in[11];
    const float* fcW   = (const float*)d_in[12];
    const float* fcb   = (const float*)d_in[13];
    const float* gam   = (const float*)d_in[14];
    const float* bet   = (const float*)d_in[15];
    const float* oW    = (const float*)d_in[16];
    const float* ob    = (const float*)d_in[17];
    float* out = (float*)d_out;

    static int smem_set = 0;
    if (!smem_set) {
        cudaFuncSetAttribute(k_trans, cudaFuncAttributeMaxDynamicSharedMemorySize, UPD_SMEM);
        smem_set = 1;
    }

    k_zero_pre<<<(NN + 255) / 256, 256>>>();
    k_linnode<<<NN / 8, 128>>>(x, lnW, lnb);
    k_deg<<<(EI + 255) / 256, 256>>>(ei, ee, pos);
    k_prepw<<<256, 256>>>(Wi, We);

    k_scan_a<<<NBLK_SCAN, 1024>>>(0);
    k_scan_a<<<NBLK_SCAN, 1024>>>(1);
    k_scan_b<<<1, 32>>>();
    k_scan_c<<<NBLK_SCAN, 1024>>>(0);
    k_scan_c<<<NBLK_SCAN, 1024>>>(1);
    k_fillf<<<(EI + 255) / 256, 256>>>(ei, ee, eattr);

    for (int l = 0; l < 4; l++) {
        k_trans<<<NBLK_UPD, 256, UPD_SMEM>>>(l, l & 1);
        k_gath2<<<(NN * 32 + 255) / 256, 256>>>(bi + l * HD, be + l * HD, batch,
                                                l & 1, l == 0, l == 3);
    }

    k_fc<<<GB, 128>>>(fcW + 0 * HD * HD, fcb + 0 * HD, gam + 0 * HD, bet + 0 * HD, 0);
    k_fc<<<GB, 128>>>(fcW + 1 * HD * HD, fcb + 1 * HD, gam + 1 * HD, bet + 1 * HD, 1);
    k_fc<<<GB, 128>>>(fcW + 2 * HD * HD, fcb + 2 * HD, gam + 2 * HD, bet + 2 * HD, 0);
    k_out<<<GB, 128>>>(oW, ob, out);
}